// round 1
// baseline (speedup 1.0000x reference)
#include <cuda_runtime.h>
#include <math.h>

// ---------------------------------------------------------------------------
// Scratch layout (floats) in one static device buffer (no allocations).
// ---------------------------------------------------------------------------
#define ST0 2097152ull   // 8*64*64*64
#define ST1 1048576ull   // 8*128*32*32
#define G0  8388608ull   // 8*256*64*64
#define G1  4194304ull   // 8*512*32*32

#define OFF_HF0 0ull
#define OFF_CF0 (OFF_HF0 + ST0)
#define OFF_HB0 (OFF_CF0 + ST0)
#define OFF_CB0 (OFF_HB0 + ST0)
#define OFF_HF1 (OFF_CB0 + ST0)
#define OFF_CF1 (OFF_HF1 + ST1)
#define OFF_HB1 (OFF_CF1 + ST1)
#define OFF_CB1 (OFF_HB1 + ST1)
#define OFF_G0F (OFF_CB1 + ST1)
#define OFF_G0B (OFF_G0F + G0)
#define OFF_G1F (OFF_G0B + G0)
#define OFF_G1B (OFF_G1F + G1)
#define BUF_TOTAL (OFF_G1B + G1)   // 37,748,736 floats = 151 MB

__device__ float g_buf[BUF_TOTAL];

#define STATE_TOTAL (OFF_G0F)      // states to zero each launch

// ---------------------------------------------------------------------------
// Zero-init kernel for the recurrent states.
// ---------------------------------------------------------------------------
__global__ void zero_kernel(float* __restrict__ p, size_t n) {
    size_t i = (size_t)blockIdx.x * blockDim.x + threadIdx.x;
    if (i < n) p[i] = 0.0f;
}

// ---------------------------------------------------------------------------
// Direct 3x3 SAME conv producing all 4C gate channels:
//   gates[b, co, y, x] = bias[co]
//      + sum_{ci<2C, ky, kx} W[co, ci, ky, kx] * in[b, ci, y+ky-1, x+kx-1]
// where in = concat(x, h) along channels (two base pointers).
//
// Tile: 64 out-channels x 16x16 spatial per block (256 threads).
// Thread: 8 co x (2 rows x 4 cols) = 64 accumulators, 4x6 input regs.
// ---------------------------------------------------------------------------
#define TCO 64
#define TSP 16

template<int C, int H, int W>
__global__ __launch_bounds__(256, 2)
void conv_gates(const float* __restrict__ x, const float* __restrict__ h,
                const float* __restrict__ Wt, const float* __restrict__ bias,
                float* __restrict__ gates)
{
    const int b      = blockIdx.z;
    const int coTile = blockIdx.y * TCO;
    const int tilesX = W / TSP;
    const int tileY  = (blockIdx.x / tilesX) * TSP;
    const int tileX  = (blockIdx.x % tilesX) * TSP;

    const int tid  = threadIdx.x;
    const int ty   = tid >> 5;       // 0..7 : co group
    const int lane = tid & 31;
    const int rp   = lane >> 2;      // 0..7 : row pair
    const int cq   = lane & 3;       // 0..3 : col quad

    __shared__ float sIn[18 * 19];   // padded stride 19
    __shared__ float sW[TCO * 9];

    float acc[8][2][4];
    #pragma unroll
    for (int k = 0; k < 8; k++)
        #pragma unroll
        for (int r = 0; r < 2; r++)
            #pragma unroll
            for (int c = 0; c < 4; c++)
                acc[k][r][c] = 0.0f;

    const float* xb = x + (size_t)b * C * H * W;
    const float* hb = h + (size_t)b * C * H * W;

    for (int ci = 0; ci < 2 * C; ++ci) {
        const float* src = (ci < C) ? (xb + (size_t)ci * H * W)
                                    : (hb + (size_t)(ci - C) * H * W);
        __syncthreads();
        // stage 18x18 input patch (zero-padded at borders)
        for (int i = tid; i < 18 * 18; i += 256) {
            int r = i / 18, c = i % 18;
            int gy = tileY - 1 + r;
            int gx = tileX - 1 + c;
            float v = 0.0f;
            if (gy >= 0 && gy < H && gx >= 0 && gx < W) v = src[gy * W + gx];
            sIn[r * 19 + c] = v;
        }
        // stage 64x9 weights for this ci
        const float* wp = Wt + ((size_t)coTile * (2 * C) + ci) * 9;
        for (int i = tid; i < TCO * 9; i += 256) {
            int col = i / 9, tap = i % 9;
            sW[i] = wp[(size_t)col * (2 * C) * 9 + tap];
        }
        __syncthreads();

        // register-cache this thread's 4x6 input footprint
        float xin[4][6];
        #pragma unroll
        for (int i = 0; i < 4; i++)
            #pragma unroll
            for (int j = 0; j < 6; j++)
                xin[i][j] = sIn[(2 * rp + i) * 19 + (4 * cq + j)];

        #pragma unroll
        for (int tap = 0; tap < 9; tap++) {
            const int ky = tap / 3, kx = tap % 3;
            #pragma unroll
            for (int k = 0; k < 8; k++) {
                const float w = sW[(ty * 8 + k) * 9 + tap];
                #pragma unroll
                for (int r = 0; r < 2; r++)
                    #pragma unroll
                    for (int c = 0; c < 4; c++)
                        acc[k][r][c] += w * xin[r + ky][c + kx];
            }
        }
    }

    // epilogue: add bias, write gates
    #pragma unroll
    for (int k = 0; k < 8; k++) {
        const int co = coTile + ty * 8 + k;
        const float bv = bias[co];
        #pragma unroll
        for (int r = 0; r < 2; r++) {
            const int y = tileY + 2 * rp + r;
            #pragma unroll
            for (int c = 0; c < 4; c++) {
                const int xx = tileX + 4 * cq + c;
                gates[((size_t)b * 4 * C + co) * H * W + (size_t)y * W + xx] =
                    acc[k][r][c] + bv;
            }
        }
    }
}

// ---------------------------------------------------------------------------
// LSTM gate update, mask-predicated per batch element.
// gates channels: [0:C)=i, [C:2C)=f, [2C:3C)=o, [3C:4C)=g
// ---------------------------------------------------------------------------
__global__ void lstm_update(const float* __restrict__ gates,
                            float* __restrict__ h, float* __restrict__ c,
                            const int* __restrict__ mask,
                            int t, int B, int C, int HW)
{
    const int total = B * C * HW;
    int idx = blockIdx.x * blockDim.x + threadIdx.x;
    if (idx >= total) return;
    const int b = idx / (C * HW);
    if (mask[t * B + b] <= 0) return;
    const int rem = idx - b * C * HW;       // c*HW + p
    const size_t base = (size_t)b * 4 * C * HW + rem;
    const size_t gstep = (size_t)C * HW;
    const float gi = gates[base];
    const float gf = gates[base + gstep];
    const float go = gates[base + 2 * gstep];
    const float gg = gates[base + 3 * gstep];
    const float si = 1.0f / (1.0f + expf(-gi));
    const float sf = 1.0f / (1.0f + expf(-gf));
    const float so = 1.0f / (1.0f + expf(-go));
    const float tg = tanhf(gg);
    const float cn = sf * c[idx] + si * tg;
    const float hn = so * tanhf(cn);
    c[idx] = cn;
    h[idx] = hn;
}

// ---------------------------------------------------------------------------
// Final output: (h_fwd + h_bwd) / 2
// ---------------------------------------------------------------------------
__global__ void avg_kernel(const float* __restrict__ a, const float* __restrict__ b,
                           float* __restrict__ out, size_t n)
{
    size_t i = (size_t)blockIdx.x * blockDim.x + threadIdx.x;
    if (i < n) out[i] = 0.5f * (a[i] + b[i]);
}

// ---------------------------------------------------------------------------
// Launch
// ---------------------------------------------------------------------------
extern "C" void kernel_launch(void* const* d_in, const int* in_sizes, int n_in,
                              void* d_out, int out_size)
{
    const float* feat0 = (const float*)d_in[0];   // [16,8,64,64,64]
    const float* feat1 = (const float*)d_in[1];   // [16,8,128,32,32]
    const int*   mask  = (const int*)  d_in[2];   // [16,8]
    const float* Wf0   = (const float*)d_in[3];
    const float* bf0   = (const float*)d_in[4];
    const float* Wb0   = (const float*)d_in[5];
    const float* bb0   = (const float*)d_in[6];
    const float* Wf1   = (const float*)d_in[7];
    const float* bf1   = (const float*)d_in[8];
    const float* Wb1   = (const float*)d_in[9];
    const float* Wb1b  = nullptr; (void)Wb1b;
    const float* bb1   = (const float*)d_in[10];
    float* out = (float*)d_out;

    float* buf = nullptr;
    cudaGetSymbolAddress((void**)&buf, g_buf);

    // zero recurrent states
    {
        const size_t n = STATE_TOTAL;
        zero_kernel<<<(unsigned)((n + 255) / 256), 256>>>(buf, n);
    }

    const int T = 16, B = 8;
    const size_t f0step = (size_t)B * 64 * 64 * 64;   // per-timestep stride
    const size_t f1step = (size_t)B * 128 * 32 * 32;

    const dim3 grid0(16, 4, 8);   // (64/16)^2 tiles, 256/64 co-tiles, B
    const dim3 grid1(4, 8, 8);    // (32/16)^2 tiles, 512/64 co-tiles, B

    const int upd0_blocks = (int)((ST0 + 255) / 256);
    const int upd1_blocks = (int)((ST1 + 255) / 256);

    for (int t = 0; t < T; ++t) {
        const float* x0 = feat0 + (size_t)t * f0step;
        const float* x1 = feat1 + (size_t)t * f1step;

        // level 0 forward cell
        conv_gates<64, 64, 64><<<grid0, 256>>>(x0, buf + OFF_HF0, Wf0, bf0, buf + OFF_G0F);
        lstm_update<<<upd0_blocks, 256>>>(buf + OFF_G0F, buf + OFF_HF0, buf + OFF_CF0,
                                          mask, t, B, 64, 64 * 64);
        // level 0 backward cell
        conv_gates<64, 64, 64><<<grid0, 256>>>(x0, buf + OFF_HB0, Wb0, bb0, buf + OFF_G0B);
        lstm_update<<<upd0_blocks, 256>>>(buf + OFF_G0B, buf + OFF_HB0, buf + OFF_CB0,
                                          mask, t, B, 64, 64 * 64);
        // level 1 forward cell
        conv_gates<128, 32, 32><<<grid1, 256>>>(x1, buf + OFF_HF1, Wf1, bf1, buf + OFF_G1F);
        lstm_update<<<upd1_blocks, 256>>>(buf + OFF_G1F, buf + OFF_HF1, buf + OFF_CF1,
                                          mask, t, B, 128, 32 * 32);
        // level 1 backward cell
        conv_gates<128, 32, 32><<<grid1, 256>>>(x1, buf + OFF_HB1, Wb1, bb1, buf + OFF_G1B);
        lstm_update<<<upd1_blocks, 256>>>(buf + OFF_G1B, buf + OFF_HB1, buf + OFF_CB1,
                                          mask, t, B, 128, 32 * 32);
    }

    avg_kernel<<<(unsigned)((ST0 + 255) / 256), 256>>>(buf + OFF_HF0, buf + OFF_HB0, out, ST0);
    avg_kernel<<<(unsigned)((ST1 + 255) / 256), 256>>>(buf + OFF_HF1, buf + OFF_HB1,
                                                       out + ST0, ST1);
}

// round 3
// speedup vs baseline: 1.4217x; 1.4217x over previous
#include <cuda_runtime.h>
#include <math.h>

// ---------------------------------------------------------------------------
// Scratch: per cell {h_ping, h_pong, c}. 4 cells.
// ---------------------------------------------------------------------------
#define ST0 2097152ull   // 8*64*64*64
#define ST1 1048576ull   // 8*128*32*32

#define OFF_HF0A 0ull
#define OFF_HF0B (OFF_HF0A + ST0)
#define OFF_CF0  (OFF_HF0B + ST0)
#define OFF_HB0A (OFF_CF0  + ST0)
#define OFF_HB0B (OFF_HB0A + ST0)
#define OFF_CB0  (OFF_HB0B + ST0)
#define OFF_HF1A (OFF_CB0  + ST0)
#define OFF_HF1B (OFF_HF1A + ST1)
#define OFF_CF1  (OFF_HF1B + ST1)
#define OFF_HB1A (OFF_CF1  + ST1)
#define OFF_HB1B (OFF_HB1A + ST1)
#define OFF_CB1  (OFF_HB1B + ST1)
#define BUF_TOTAL (OFF_CB1 + ST1)   // 18.87M floats = 75.5 MB

__device__ float g_buf[BUF_TOTAL];

__global__ void zero_kernel(float* __restrict__ p, size_t n) {
    size_t i = (size_t)blockIdx.x * blockDim.x + threadIdx.x;
    if (i < n) p[i] = 0.0f;
}

// ---------------------------------------------------------------------------
// Fused ConvLSTM cell step (race-free: reads h_in, writes h_out; c in-place).
//
// Block: 16 channels-of-C x 4 gates = 64 conv outputs over a 16x16 tile for
// one batch element, 256 threads. Thread output o = k*8+ty (k=0..7):
//   gate = o>>4, chan = o&15  -> each thread holds all 4 gates for channels
// {coBase+ty, coBase+8+ty} at its 2x4 pixels -> LSTM update in registers.
//
// mask==0: copy owned h region h_in->h_out, leave c; skip conv entirely.
// ---------------------------------------------------------------------------
#define TSP 16
#define CI_BLK 4

template<int C, int H, int W>
__global__ __launch_bounds__(256, 2)
void convlstm_step(const float* __restrict__ x,
                   const float* __restrict__ h_in,
                   float* __restrict__ h_out,
                   float* __restrict__ c,
                   const float* __restrict__ Wt, const float* __restrict__ bias,
                   const int* __restrict__ mask_t)
{
    const int b = blockIdx.z;
    const int coBase = blockIdx.y * 16;
    const int tilesX = W / TSP;
    const int tileY  = (blockIdx.x / tilesX) * TSP;
    const int tileX  = (blockIdx.x % tilesX) * TSP;
    const int tid  = threadIdx.x;

    if (mask_t[b] <= 0) {
        // copy owned region: 16 channels x 16x16 pixels = 4096 elems
        for (int i = tid; i < 16 * TSP * TSP; i += 256) {
            const int chL = i >> 8;
            const int rem = i & 255;
            const int y = tileY + (rem >> 4);
            const int xx = tileX + (rem & 15);
            const size_t idx = ((size_t)b * C + coBase + chL) * (size_t)(H * W)
                             + (size_t)y * W + xx;
            h_out[idx] = h_in[idx];
        }
        return;
    }

    const int ty   = tid >> 5;       // 0..7
    const int lane = tid & 31;
    const int rp   = lane >> 2;      // 0..7 : row pair
    const int cq   = lane & 3;       // 0..3 : col quad

    __shared__ float sIn[CI_BLK][18 * 19];      // padded stride 19
    __shared__ float sW[CI_BLK * 64 * 9];

    float acc[8][2][4];
    #pragma unroll
    for (int k = 0; k < 8; k++)
        #pragma unroll
        for (int r = 0; r < 2; r++)
            #pragma unroll
            for (int cc = 0; cc < 4; cc++)
                acc[k][r][cc] = 0.0f;

    const float* xb = x + (size_t)b * C * H * W;
    const float* hb = h_in + (size_t)b * C * H * W;

    for (int ci0 = 0; ci0 < 2 * C; ci0 += CI_BLK) {
        __syncthreads();
        // stage CI_BLK 18x18 input patches (zero-padded at borders)
        for (int i = tid; i < CI_BLK * 324; i += 256) {
            const int ciL = i / 324;
            const int rem = i - ciL * 324;
            const int r = rem / 18, cc = rem - r * 18;
            const int ci = ci0 + ciL;
            const float* src = (ci < C) ? (xb + (size_t)ci * H * W)
                                        : (hb + (size_t)(ci - C) * H * W);
            const int gy = tileY - 1 + r;
            const int gx = tileX - 1 + cc;
            float v = 0.0f;
            if (gy >= 0 && gy < H && gx >= 0 && gx < W) v = src[gy * W + gx];
            sIn[ciL][r * 19 + cc] = v;
        }
        // stage CI_BLK x 64 x 9 weights (o -> row gate*C + coBase + ch)
        for (int i = tid; i < CI_BLK * 576; i += 256) {
            const int ciL = i / 576;
            const int rem = i - ciL * 576;
            const int o = rem / 9, tap = rem - o * 9;
            const int row = (o >> 4) * C + coBase + (o & 15);
            sW[i] = Wt[((size_t)row * (2 * C) + (ci0 + ciL)) * 9 + tap];
        }
        __syncthreads();

        #pragma unroll
        for (int ciL = 0; ciL < CI_BLK; ciL++) {
            float xin[4][6];
            #pragma unroll
            for (int i = 0; i < 4; i++)
                #pragma unroll
                for (int j = 0; j < 6; j++)
                    xin[i][j] = sIn[ciL][(2 * rp + i) * 19 + (4 * cq + j)];

            const float* wci = sW + ciL * 576;
            #pragma unroll
            for (int tap = 0; tap < 9; tap++) {
                const int ky = tap / 3, kx = tap % 3;
                #pragma unroll
                for (int k = 0; k < 8; k++) {
                    const float w = wci[(k * 8 + ty) * 9 + tap];  // broadcast
                    #pragma unroll
                    for (int r = 0; r < 2; r++)
                        #pragma unroll
                        for (int cc = 0; cc < 4; cc++)
                            acc[k][r][cc] += w * xin[r + ky][cc + kx];
                }
            }
        }
    }

    // ---- fused LSTM epilogue (in registers) ----
    #pragma unroll
    for (int j = 0; j < 2; j++) {
        const int ch = coBase + j * 8 + ty;
        const float bi = bias[0 * C + ch];
        const float bf = bias[1 * C + ch];
        const float bo = bias[2 * C + ch];
        const float bg = bias[3 * C + ch];
        #pragma unroll
        for (int r = 0; r < 2; r++) {
            const int y = tileY + 2 * rp + r;
            #pragma unroll
            for (int cc = 0; cc < 4; cc++) {
                const int xx = tileX + 4 * cq + cc;
                const size_t idx = ((size_t)b * C + ch) * (size_t)(H * W)
                                 + (size_t)y * W + xx;
                const float gi = acc[0 + j][r][cc] + bi;
                const float gf = acc[2 + j][r][cc] + bf;
                const float go = acc[4 + j][r][cc] + bo;
                const float gg = acc[6 + j][r][cc] + bg;
                const float si = 1.0f / (1.0f + __expf(-gi));
                const float sf = 1.0f / (1.0f + __expf(-gf));
                const float so = 1.0f / (1.0f + __expf(-go));
                const float tg = tanhf(gg);
                const float cn = sf * c[idx] + si * tg;
                c[idx] = cn;
                h_out[idx] = so * tanhf(cn);
            }
        }
    }
}

__global__ void avg_kernel(const float* __restrict__ a, const float* __restrict__ b,
                           float* __restrict__ out, size_t n)
{
    size_t i = (size_t)blockIdx.x * blockDim.x + threadIdx.x;
    if (i < n) out[i] = 0.5f * (a[i] + b[i]);
}

// ---------------------------------------------------------------------------
// Launch
// ---------------------------------------------------------------------------
extern "C" void kernel_launch(void* const* d_in, const int* in_sizes, int n_in,
                              void* d_out, int out_size)
{
    const float* feat0 = (const float*)d_in[0];   // [16,8,64,64,64]
    const float* feat1 = (const float*)d_in[1];   // [16,8,128,32,32]
    const int*   mask  = (const int*)  d_in[2];   // [16,8]
    const float* Wf0   = (const float*)d_in[3];
    const float* bf0   = (const float*)d_in[4];
    const float* Wb0   = (const float*)d_in[5];
    const float* bb0   = (const float*)d_in[6];
    const float* Wf1   = (const float*)d_in[7];
    const float* bf1   = (const float*)d_in[8];
    const float* Wb1   = (const float*)d_in[9];
    const float* bb1   = (const float*)d_in[10];
    float* out = (float*)d_out;

    float* buf = nullptr;
    cudaGetSymbolAddress((void**)&buf, g_buf);

    zero_kernel<<<(unsigned)((BUF_TOTAL + 255) / 256), 256>>>(buf, BUF_TOTAL);

    const int T = 16, B = 8;
    const size_t f0step = (size_t)B * 64 * 64 * 64;
    const size_t f1step = (size_t)B * 128 * 32 * 32;

    const dim3 grid0(16, 64 / 16, 8);
    const dim3 grid1(4, 128 / 16, 8);

    float* hf0[2] = { buf + OFF_HF0A, buf + OFF_HF0B };
    float* hb0[2] = { buf + OFF_HB0A, buf + OFF_HB0B };
    float* hf1[2] = { buf + OFF_HF1A, buf + OFF_HF1B };
    float* hb1[2] = { buf + OFF_HB1A, buf + OFF_HB1B };

    for (int t = 0; t < T; ++t) {
        const float* x0 = feat0 + (size_t)t * f0step;
        const float* x1 = feat1 + (size_t)t * f1step;
        const int* mt = mask + t * B;
        const int p = t & 1, q = p ^ 1;

        convlstm_step<64, 64, 64><<<grid0, 256>>>(x0, hf0[p], hf0[q], buf + OFF_CF0,
                                                  Wf0, bf0, mt);
        convlstm_step<64, 64, 64><<<grid0, 256>>>(x0, hb0[p], hb0[q], buf + OFF_CB0,
                                                  Wb0, bb0, mt);
        convlstm_step<128, 32, 32><<<grid1, 256>>>(x1, hf1[p], hf1[q], buf + OFF_CF1,
                                                   Wf1, bf1, mt);
        convlstm_step<128, 32, 32><<<grid1, 256>>>(x1, hb1[p], hb1[q], buf + OFF_CB1,
                                                   Wb1, bb1, mt);
    }

    // T=16 even: final states are back in the 'A' (ping) buffers.
    avg_kernel<<<(unsigned)((ST0 + 255) / 256), 256>>>(hf0[0], hb0[0], out, ST0);
    avg_kernel<<<(unsigned)((ST1 + 255) / 256), 256>>>(hf1[0], hb1[0], out + ST0, ST1);
}

// round 5
// speedup vs baseline: 3.5070x; 2.4668x over previous
#include <cuda_runtime.h>
#include <cstdint>
#include <math.h>

// ---------------------------------------------------------------------------
// Scratch: per cell {h_ping, h_pong, c} + pre-transposed weights.
// ---------------------------------------------------------------------------
#define ST0 2097152ull   // 8*64*64*64
#define ST1 1048576ull   // 8*128*32*32
#define WT0_SZ (72ull * 64 * 64)     // (C/16)*2C*64*9 = 72*C^2 ; C=64
#define WT1_SZ (72ull * 128 * 128)   // C=128

#define OFF_HF0A 0ull
#define OFF_HF0B (OFF_HF0A + ST0)
#define OFF_CF0  (OFF_HF0B + ST0)
#define OFF_HB0A (OFF_CF0  + ST0)
#define OFF_HB0B (OFF_HB0A + ST0)
#define OFF_CB0  (OFF_HB0B + ST0)
#define OFF_HF1A (OFF_CB0  + ST0)
#define OFF_HF1B (OFF_HF1A + ST1)
#define OFF_CF1  (OFF_HF1B + ST1)
#define OFF_HB1A (OFF_CF1  + ST1)
#define OFF_HB1B (OFF_HB1A + ST1)
#define OFF_CB1  (OFF_HB1B + ST1)
#define OFF_WTF0 (OFF_CB1  + ST1)
#define OFF_WTB0 (OFF_WTF0 + WT0_SZ)
#define OFF_WTF1 (OFF_WTB0 + WT0_SZ)
#define OFF_WTB1 (OFF_WTF1 + WT1_SZ)
#define BUF_TOTAL (OFF_WTB1 + WT1_SZ)

__device__ float g_buf[BUF_TOTAL];

#define STATE_TOTAL (OFF_WTF0)

__global__ void zero_kernel(float* __restrict__ p, size_t n) {
    size_t i = (size_t)blockIdx.x * blockDim.x + threadIdx.x;
    if (i < n) p[i] = 0.0f;
}

// ---------------------------------------------------------------------------
// One-time weight transpose into per-group contiguous layout:
//   WT[((g*2C + ci)*64 + o)*9 + tap] = W[row(o,g)][ci][tap]
//   row(o,g) = (o>>4)*C + g*16 + (o&15)
// ---------------------------------------------------------------------------
template<int C>
__global__ void transpose_weights(const float* __restrict__ W, float* __restrict__ WT)
{
    const int total = (C / 16) * 2 * C * 64 * 9;
    int i = blockIdx.x * 256 + threadIdx.x;
    if (i >= total) return;
    int tap = i % 9;
    int r = i / 9;
    int o = r % 64; r /= 64;
    int ci = r % (2 * C);
    int g = r / (2 * C);
    int row = (o >> 4) * C + g * 16 + (o & 15);
    WT[i] = W[((size_t)row * (2 * C) + ci) * 9 + tap];
}

// ---------------------------------------------------------------------------
// cp.async helpers
// ---------------------------------------------------------------------------
__device__ __forceinline__ void cpa16(unsigned int dst, const float* src) {
    asm volatile("cp.async.cg.shared.global [%0], [%1], 16;" :: "r"(dst), "l"(src));
}
__device__ __forceinline__ void cpa4z(unsigned int dst, const float* src, bool v) {
    int sz = v ? 4 : 0;
    asm volatile("cp.async.ca.shared.global [%0], [%1], 4, %2;"
                 :: "r"(dst), "l"(src), "r"(sz));
}
__device__ __forceinline__ void cpa_commit() {
    asm volatile("cp.async.commit_group;" ::: "memory");
}

// ---------------------------------------------------------------------------
// Fused ConvLSTM cell step, cp.async double-buffered.
// Block: 64 conv outputs (= 4 gates x 16 channels) x 16x16 tile x 1 batch.
// Thread: 8 outputs x (2x4) pixels. Epilogue does the LSTM update in regs.
// mask==0: copy owned h region h_in->h_out, c untouched, conv skipped.
// ---------------------------------------------------------------------------
#define TSP 16
#define CI_BLK 4

template<int C, int H, int W>
__global__ __launch_bounds__(256, 2)
void convlstm_step(const float* __restrict__ x,
                   const float* __restrict__ h_in,
                   float* __restrict__ h_out,
                   float* __restrict__ c,
                   const float* __restrict__ WT, const float* __restrict__ bias,
                   const int* __restrict__ mask_t)
{
    const int b = blockIdx.z;
    const int coGrp = blockIdx.y;
    const int coBase = coGrp * 16;
    const int tilesX = W / TSP;
    const int tileY  = (blockIdx.x / tilesX) * TSP;
    const int tileX  = (blockIdx.x % tilesX) * TSP;
    const int tid  = threadIdx.x;

    if (mask_t[b] <= 0) {
        for (int i = tid; i < 16 * TSP * TSP; i += 256) {
            const int chL = i >> 8;
            const int rem = i & 255;
            const int y = tileY + (rem >> 4);
            const int xx = tileX + (rem & 15);
            const size_t idx = ((size_t)b * C + coBase + chL) * (size_t)(H * W)
                             + (size_t)y * W + xx;
            h_out[idx] = h_in[idx];
        }
        return;
    }

    const int ty   = tid >> 5;
    const int lane = tid & 31;
    const int rp   = lane >> 2;
    const int cq   = lane & 3;

    __shared__ __align__(16) float sIn[2][CI_BLK][342];     // 18*19
    __shared__ __align__(16) float sW[2][CI_BLK * 576];

    const unsigned int sInAddr = (unsigned int)__cvta_generic_to_shared(&sIn[0][0][0]);
    const unsigned int sWAddr  = (unsigned int)__cvta_generic_to_shared(&sW[0][0]);

    float acc[8][2][4];
    #pragma unroll
    for (int k = 0; k < 8; k++)
        #pragma unroll
        for (int r = 0; r < 2; r++)
            #pragma unroll
            for (int cc = 0; cc < 4; cc++)
                acc[k][r][cc] = 0.0f;

    const float* xb = x + (size_t)b * C * H * W;
    const float* hb = h_in + (size_t)b * C * H * W;

    const int NBLK = (2 * C) / CI_BLK;

    auto stage = [&](int ci0s, int dbuf) {
        // input patches: CI_BLK x 18x18, 4B cp.async with zero-fill OOB
        for (int i = tid; i < CI_BLK * 324; i += 256) {
            const int ciL = i / 324;
            const int rem = i - ciL * 324;
            const int r = rem / 18, cc = rem - r * 18;
            const int ci = ci0s + ciL;
            const float* srcp = (ci < C) ? (xb + (size_t)ci * H * W)
                                         : (hb + (size_t)(ci - C) * H * W);
            const int gy = tileY - 1 + r;
            const int gx = tileX - 1 + cc;
            const bool v = (gy >= 0 && gy < H && gx >= 0 && gx < W);
            const float* sp = v ? (srcp + gy * W + gx) : srcp;
            cpa4z(sInAddr + (unsigned int)(((dbuf * CI_BLK + ciL) * 342 + r * 19 + cc) * 4),
                  sp, v);
        }
        // weights: CI_BLK*576 contiguous floats, 16B cp.async
        const float* wsrc = WT + ((size_t)(coGrp * 2 * C + ci0s)) * 576;
        for (int i = tid; i < (CI_BLK * 576) / 4; i += 256) {
            cpa16(sWAddr + (unsigned int)((dbuf * CI_BLK * 576 + i * 4) * 4), wsrc + i * 4);
        }
        cpa_commit();
    };

    stage(0, 0);

    for (int blk = 0; blk < NBLK; ++blk) {
        const int cur = blk & 1;
        if (blk + 1 < NBLK) {
            stage((blk + 1) * CI_BLK, cur ^ 1);
            asm volatile("cp.async.wait_group 1;" ::: "memory");
        } else {
            asm volatile("cp.async.wait_group 0;" ::: "memory");
        }
        __syncthreads();

        #pragma unroll
        for (int ciL = 0; ciL < CI_BLK; ciL++) {
            float xin[4][6];
            #pragma unroll
            for (int i = 0; i < 4; i++)
                #pragma unroll
                for (int j = 0; j < 6; j++)
                    xin[i][j] = sIn[cur][ciL][(2 * rp + i) * 19 + (4 * cq + j)];

            const float* wci = &sW[cur][ciL * 576];
            #pragma unroll
            for (int tap = 0; tap < 9; tap++) {
                const int ky = tap / 3, kx = tap % 3;
                #pragma unroll
                for (int k = 0; k < 8; k++) {
                    const float w = wci[(k * 8 + ty) * 9 + tap];  // broadcast
                    #pragma unroll
                    for (int r = 0; r < 2; r++)
                        #pragma unroll
                        for (int cc = 0; cc < 4; cc++)
                            acc[k][r][cc] += w * xin[r + ky][cc + kx];
                }
            }
        }
        __syncthreads();
    }

    // ---- fused LSTM epilogue ----
    #pragma unroll
    for (int j = 0; j < 2; j++) {
        const int ch = coBase + j * 8 + ty;
        const float bi = bias[0 * C + ch];
        const float bf = bias[1 * C + ch];
        const float bo = bias[2 * C + ch];
        const float bg = bias[3 * C + ch];
        #pragma unroll
        for (int r = 0; r < 2; r++) {
            const int y = tileY + 2 * rp + r;
            #pragma unroll
            for (int cc = 0; cc < 4; cc++) {
                const int xx = tileX + 4 * cq + cc;
                const size_t idx = ((size_t)b * C + ch) * (size_t)(H * W)
                                 + (size_t)y * W + xx;
                const float gi = acc[0 + j][r][cc] + bi;
                const float gf = acc[2 + j][r][cc] + bf;
                const float go = acc[4 + j][r][cc] + bo;
                const float gg = acc[6 + j][r][cc] + bg;
                const float si = 1.0f / (1.0f + __expf(-gi));
                const float sf = 1.0f / (1.0f + __expf(-gf));
                const float so = 1.0f / (1.0f + __expf(-go));
                const float tg = tanhf(gg);
                const float cn = sf * c[idx] + si * tg;
                c[idx] = cn;
                h_out[idx] = so * tanhf(cn);
            }
        }
    }
}

__global__ void avg_kernel(const float* __restrict__ a, const float* __restrict__ b,
                           float* __restrict__ out, size_t n)
{
    size_t i = (size_t)blockIdx.x * blockDim.x + threadIdx.x;
    if (i < n) out[i] = 0.5f * (a[i] + b[i]);
}

// ---------------------------------------------------------------------------
// Launch: 4 independent cell chains forked onto 3 extra non-blocking streams.
// ---------------------------------------------------------------------------
extern "C" void kernel_launch(void* const* d_in, const int* in_sizes, int n_in,
                              void* d_out, int out_size)
{
    const float* feat0 = (const float*)d_in[0];
    const float* feat1 = (const float*)d_in[1];
    const int*   mask  = (const int*)  d_in[2];
    const float* Wf0   = (const float*)d_in[3];
    const float* bf0   = (const float*)d_in[4];
    const float* Wb0   = (const float*)d_in[5];
    const float* bb0   = (const float*)d_in[6];
    const float* Wf1   = (const float*)d_in[7];
    const float* bf1   = (const float*)d_in[8];
    const float* Wb1   = (const float*)d_in[9];
    const float* bb1   = (const float*)d_in[10];
    float* out = (float*)d_out;

    float* buf = nullptr;
    cudaGetSymbolAddress((void**)&buf, g_buf);

    static cudaStream_t strm[3];
    static cudaEvent_t evFork, evJoin[3];
    static bool inited = false;
    if (!inited) {
        for (int i = 0; i < 3; i++)
            cudaStreamCreateWithFlags(&strm[i], cudaStreamNonBlocking);
        cudaEventCreateWithFlags(&evFork, cudaEventDisableTiming);
        for (int i = 0; i < 3; i++)
            cudaEventCreateWithFlags(&evJoin[i], cudaEventDisableTiming);
        inited = true;
    }

    // init + weight transposes on the main stream
    zero_kernel<<<(unsigned)((STATE_TOTAL + 255) / 256), 256>>>(buf, STATE_TOTAL);
    {
        const int t0 = (int)WT0_SZ, t1 = (int)WT1_SZ;
        transpose_weights<64><<<(t0 + 255) / 256, 256>>>(Wf0, buf + OFF_WTF0);
        transpose_weights<64><<<(t0 + 255) / 256, 256>>>(Wb0, buf + OFF_WTB0);
        transpose_weights<128><<<(t1 + 255) / 256, 256>>>(Wf1, buf + OFF_WTF1);
        transpose_weights<128><<<(t1 + 255) / 256, 256>>>(Wb1, buf + OFF_WTB1);
    }
    cudaEventRecord(evFork, 0);
    for (int i = 0; i < 3; i++) cudaStreamWaitEvent(strm[i], evFork, 0);

    const int T = 16, B = 8;
    const size_t f0step = (size_t)B * 64 * 64 * 64;
    const size_t f1step = (size_t)B * 128 * 32 * 32;
    const dim3 grid0(16, 64 / 16, 8);
    const dim3 grid1(4, 128 / 16, 8);

    float* hf0[2] = { buf + OFF_HF0A, buf + OFF_HF0B };
    float* hb0[2] = { buf + OFF_HB0A, buf + OFF_HB0B };
    float* hf1[2] = { buf + OFF_HF1A, buf + OFF_HF1B };
    float* hb1[2] = { buf + OFF_HB1A, buf + OFF_HB1B };

    // chain F0 on the main stream
    for (int t = 0; t < T; ++t) {
        const int p = t & 1, q = p ^ 1;
        convlstm_step<64, 64, 64><<<grid0, 256>>>(
            feat0 + (size_t)t * f0step, hf0[p], hf0[q], buf + OFF_CF0,
            buf + OFF_WTF0, bf0, mask + t * B);
    }
    // chain B0 on strm[0]
    for (int t = 0; t < T; ++t) {
        const int p = t & 1, q = p ^ 1;
        convlstm_step<64, 64, 64><<<grid0, 256, 0, strm[0]>>>(
            feat0 + (size_t)t * f0step, hb0[p], hb0[q], buf + OFF_CB0,
            buf + OFF_WTB0, bb0, mask + t * B);
    }
    // chain F1 on strm[1]
    for (int t = 0; t < T; ++t) {
        const int p = t & 1, q = p ^ 1;
        convlstm_step<128, 32, 32><<<grid1, 256, 0, strm[1]>>>(
            feat1 + (size_t)t * f1step, hf1[p], hf1[q], buf + OFF_CF1,
            buf + OFF_WTF1, bf1, mask + t * B);
    }
    // chain B1 on strm[2]
    for (int t = 0; t < T; ++t) {
        const int p = t & 1, q = p ^ 1;
        convlstm_step<128, 32, 32><<<grid1, 256, 0, strm[2]>>>(
            feat1 + (size_t)t * f1step, hb1[p], hb1[q], buf + OFF_CB1,
            buf + OFF_WTB1, bb1, mask + t * B);
    }

    for (int i = 0; i < 3; i++) {
        cudaEventRecord(evJoin[i], strm[i]);
        cudaStreamWaitEvent(0, evJoin[i], 0);
    }

    // T=16 even: final states are in the 'A' buffers.
    avg_kernel<<<(unsigned)((ST0 + 255) / 256), 256>>>(hf0[0], hb0[0], out, ST0);
    avg_kernel<<<(unsigned)((ST1 + 255) / 256), 256>>>(hf1[0], hb1[0], out + ST0, ST1);
}

// round 7
// speedup vs baseline: 3.5468x; 1.0114x over previous
#include <cuda_runtime.h>
#include <cstdint>
#include <math.h>

// ---------------------------------------------------------------------------
// Scratch: per cell {h_ping, h_pong, c} + pre-transposed, pair-splatted weights.
// ---------------------------------------------------------------------------
#define ST0 2097152ull   // 8*64*64*64
#define ST1 1048576ull   // 8*128*32*32
#define WT0_SZ (2ull * 72 * 64 * 64)     // splatted pairs, C=64
#define WT1_SZ (2ull * 72 * 128 * 128)   // C=128

#define OFF_HF0A 0ull
#define OFF_HF0B (OFF_HF0A + ST0)
#define OFF_CF0  (OFF_HF0B + ST0)
#define OFF_HB0A (OFF_CF0  + ST0)
#define OFF_HB0B (OFF_HB0A + ST0)
#define OFF_CB0  (OFF_HB0B + ST0)
#define OFF_HF1A (OFF_CB0  + ST0)
#define OFF_HF1B (OFF_HF1A + ST1)
#define OFF_CF1  (OFF_HF1B + ST1)
#define OFF_HB1A (OFF_CF1  + ST1)
#define OFF_HB1B (OFF_HB1A + ST1)
#define OFF_CB1  (OFF_HB1B + ST1)
#define OFF_WTF0 (OFF_CB1  + ST1)
#define OFF_WTB0 (OFF_WTF0 + WT0_SZ)
#define OFF_WTF1 (OFF_WTB0 + WT0_SZ)
#define OFF_WTB1 (OFF_WTF1 + WT1_SZ)
#define BUF_TOTAL (OFF_WTB1 + WT1_SZ)

__device__ float g_buf[BUF_TOTAL];

#define STATE_TOTAL (OFF_WTF0)

__global__ void zero_kernel(float* __restrict__ p, size_t n) {
    size_t i = (size_t)blockIdx.x * blockDim.x + threadIdx.x;
    if (i < n) p[i] = 0.0f;
}

// ---------------------------------------------------------------------------
// One-time weight transpose into per-group contiguous layout, each weight
// duplicated into an (w,w) pair for f32x2 FMA:
//   WT2[2*(((g*2C + ci)*64 + o)*9 + tap) + {0,1}] = W[row(o,g)][ci][tap]
//   row(o,g) = (o>>4)*C + g*16 + (o&15)
// ---------------------------------------------------------------------------
template<int C>
__global__ void transpose_weights(const float* __restrict__ W, float* __restrict__ WT2)
{
    const int total = (C / 16) * 2 * C * 64 * 9;
    int i = blockIdx.x * 256 + threadIdx.x;
    if (i >= total) return;
    int tap = i % 9;
    int r = i / 9;
    int o = r % 64; r /= 64;
    int ci = r % (2 * C);
    int g = r / (2 * C);
    int row = (o >> 4) * C + g * 16 + (o & 15);
    float w = W[((size_t)row * (2 * C) + ci) * 9 + tap];
    reinterpret_cast<float2*>(WT2)[i] = make_float2(w, w);
}

// ---------------------------------------------------------------------------
// cp.async + f32x2 helpers
// ---------------------------------------------------------------------------
__device__ __forceinline__ void cpa16(unsigned int dst, const float* src) {
    asm volatile("cp.async.cg.shared.global [%0], [%1], 16;" :: "r"(dst), "l"(src));
}
__device__ __forceinline__ void cpa4z(unsigned int dst, const float* src, bool v) {
    int sz = v ? 4 : 0;
    asm volatile("cp.async.ca.shared.global [%0], [%1], 4, %2;"
                 :: "r"(dst), "l"(src), "r"(sz));
}
__device__ __forceinline__ void cpa_commit() {
    asm volatile("cp.async.commit_group;" ::: "memory");
}
__device__ __forceinline__ unsigned long long pack2(float lo, float hi) {
    unsigned long long r;
    asm("mov.b64 %0, {%1, %2};" : "=l"(r) : "f"(lo), "f"(hi));
    return r;
}
__device__ __forceinline__ void fma2(unsigned long long& d,
                                     unsigned long long a, unsigned long long b) {
    asm("fma.rn.f32x2 %0, %1, %2, %0;" : "+l"(d) : "l"(a), "l"(b));
}
__device__ __forceinline__ void unpack2(unsigned long long v, float& lo, float& hi) {
    asm("mov.b64 {%0, %1}, %2;" : "=f"(lo), "=f"(hi) : "l"(v));
}

// ---------------------------------------------------------------------------
// Fused ConvLSTM cell step, cp.async double-buffered, f32x2 packed FMA.
// Block: 64 conv outputs (= 4 gates x 16 channels) x 16x16 tile x 1 batch.
// Thread: 8 outputs x (2 rows x 2 col-pairs). LSTM update in registers.
// mask==0: copy owned h region h_in->h_out, c untouched, conv skipped.
// ---------------------------------------------------------------------------
#define TSP 16
#define CI_BLK 4

template<int C, int H, int W>
__global__ __launch_bounds__(256, 2)
void convlstm_step(const float* __restrict__ x,
                   const float* __restrict__ h_in,
                   float* __restrict__ h_out,
                   float* __restrict__ c,
                   const float* __restrict__ WT2, const float* __restrict__ bias,
                   const int* __restrict__ mask_t)
{
    const int b = blockIdx.z;
    const int coGrp = blockIdx.y;
    const int coBase = coGrp * 16;
    const int tilesX = W / TSP;
    const int tileY  = (blockIdx.x / tilesX) * TSP;
    const int tileX  = (blockIdx.x % tilesX) * TSP;
    const int tid  = threadIdx.x;

    if (mask_t[b] <= 0) {
        for (int i = tid; i < 16 * TSP * TSP; i += 256) {
            const int chL = i >> 8;
            const int rem = i & 255;
            const int y = tileY + (rem >> 4);
            const int xx = tileX + (rem & 15);
            const size_t idx = ((size_t)b * C + coBase + chL) * (size_t)(H * W)
                             + (size_t)y * W + xx;
            h_out[idx] = h_in[idx];
        }
        return;
    }

    const int ty   = tid >> 5;
    const int lane = tid & 31;
    const int rp   = lane >> 2;
    const int cq   = lane & 3;

    __shared__ __align__(16) float sIn[2][CI_BLK][342];        // 18*19
    __shared__ __align__(16) float sW[2][CI_BLK * 1152];       // (w,w) pairs

    const unsigned int sInAddr = (unsigned int)__cvta_generic_to_shared(&sIn[0][0][0]);
    const unsigned int sWAddr  = (unsigned int)__cvta_generic_to_shared(&sW[0][0]);

    unsigned long long acc2[8][2][2];
    #pragma unroll
    for (int k = 0; k < 8; k++)
        #pragma unroll
        for (int r = 0; r < 2; r++)
            #pragma unroll
            for (int cc = 0; cc < 2; cc++)
                acc2[k][r][cc] = 0ull;

    const float* xb = x + (size_t)b * C * H * W;
    const float* hb = h_in + (size_t)b * C * H * W;

    const int NBLK = (2 * C) / CI_BLK;

    auto stage = [&](int ci0s, int dbuf) {
        // input patches: CI_BLK x 18x18, 4B cp.async with zero-fill OOB
        for (int i = tid; i < CI_BLK * 324; i += 256) {
            const int ciL = i / 324;
            const int rem = i - ciL * 324;
            const int r = rem / 18, cc = rem - r * 18;
            const int ci = ci0s + ciL;
            const float* srcp = (ci < C) ? (xb + (size_t)ci * H * W)
                                         : (hb + (size_t)(ci - C) * H * W);
            const int gy = tileY - 1 + r;
            const int gx = tileX - 1 + cc;
            const bool v = (gy >= 0 && gy < H && gx >= 0 && gx < W);
            const float* sp = v ? (srcp + gy * W + gx) : srcp;
            cpa4z(sInAddr + (unsigned int)(((dbuf * CI_BLK + ciL) * 342 + r * 19 + cc) * 4),
                  sp, v);
        }
        // weights: CI_BLK*1152 contiguous floats (pairs), 16B cp.async
        const float* wsrc = WT2 + ((size_t)(coGrp * 2 * C + ci0s)) * 1152;
        for (int i = tid; i < (CI_BLK * 1152) / 4; i += 256) {
            cpa16(sWAddr + (unsigned int)((dbuf * CI_BLK * 1152 + i * 4) * 4), wsrc + i * 4);
        }
        cpa_commit();
    };

    stage(0, 0);

    for (int blk = 0; blk < NBLK; ++blk) {
        const int cur = blk & 1;
        if (blk + 1 < NBLK) {
            stage((blk + 1) * CI_BLK, cur ^ 1);
            asm volatile("cp.async.wait_group 1;" ::: "memory");
        } else {
            asm volatile("cp.async.wait_group 0;" ::: "memory");
        }
        __syncthreads();

        #pragma unroll
        for (int ciL = 0; ciL < CI_BLK; ciL++) {
            // build 4 rows x 5 overlapping column pairs of this thread's input
            unsigned long long xp[4][5];
            #pragma unroll
            for (int i = 0; i < 4; i++) {
                float xs[6];
                #pragma unroll
                for (int j = 0; j < 6; j++)
                    xs[j] = sIn[cur][ciL][(2 * rp + i) * 19 + (4 * cq + j)];
                #pragma unroll
                for (int j = 0; j < 5; j++)
                    xp[i][j] = pack2(xs[j], xs[j + 1]);
            }

            const unsigned long long* wci =
                reinterpret_cast<const unsigned long long*>(&sW[cur][ciL * 1152]);
            #pragma unroll
            for (int tap = 0; tap < 9; tap++) {
                const int ky = tap / 3, kx = tap % 3;
                #pragma unroll
                for (int k = 0; k < 8; k++) {
                    const unsigned long long w2 = wci[(k * 8 + ty) * 9 + tap];
                    fma2(acc2[k][0][0], xp[ky][kx],     w2);
                    fma2(acc2[k][0][1], xp[ky][kx + 2], w2);
                    fma2(acc2[k][1][0], xp[ky + 1][kx],     w2);
                    fma2(acc2[k][1][1], xp[ky + 1][kx + 2], w2);
                }
            }
        }
        __syncthreads();
    }

    // ---- fused LSTM epilogue ----
    #pragma unroll
    for (int j = 0; j < 2; j++) {
        const int ch = coBase + j * 8 + ty;
        const float bi = bias[0 * C + ch];
        const float bf = bias[1 * C + ch];
        const float bo = bias[2 * C + ch];
        const float bg = bias[3 * C + ch];
        #pragma unroll
        for (int r = 0; r < 2; r++) {
            const int y = tileY + 2 * rp + r;
            #pragma unroll
            for (int cp = 0; cp < 2; cp++) {
                float a_i[2], a_f[2], a_o[2], a_g[2];
                unpack2(acc2[0 + j][r][cp], a_i[0], a_i[1]);
                unpack2(acc2[2 + j][r][cp], a_f[0], a_f[1]);
                unpack2(acc2[4 + j][r][cp], a_o[0], a_o[1]);
                unpack2(acc2[6 + j][r][cp], a_g[0], a_g[1]);
                #pragma unroll
                for (int u = 0; u < 2; u++) {
                    const int xx = tileX + 4 * cq + cp * 2 + u;
                    const size_t idx = ((size_t)b * C + ch) * (size_t)(H * W)
                                     + (size_t)y * W + xx;
                    const float gi = a_i[u] + bi;
                    const float gf = a_f[u] + bf;
                    const float go = a_o[u] + bo;
                    const float gg = a_g[u] + bg;
                    const float si = 1.0f / (1.0f + __expf(-gi));
                    const float sf = 1.0f / (1.0f + __expf(-gf));
                    const float so = 1.0f / (1.0f + __expf(-go));
                    const float tg = tanhf(gg);
                    const float cn = sf * c[idx] + si * tg;
                    c[idx] = cn;
                    h_out[idx] = so * tanhf(cn);
                }
            }
        }
    }
}

__global__ void avg_kernel(const float* __restrict__ a, const float* __restrict__ b,
                           float* __restrict__ out, size_t n)
{
    size_t i = (size_t)blockIdx.x * blockDim.x + threadIdx.x;
    if (i < n) out[i] = 0.5f * (a[i] + b[i]);
}

// ---------------------------------------------------------------------------
// Launch: 4 independent cell chains forked onto 3 extra non-blocking streams.
// ---------------------------------------------------------------------------
extern "C" void kernel_launch(void* const* d_in, const int* in_sizes, int n_in,
                              void* d_out, int out_size)
{
    const float* feat0 = (const float*)d_in[0];
    const float* feat1 = (const float*)d_in[1];
    const int*   mask  = (const int*)  d_in[2];
    const float* Wf0   = (const float*)d_in[3];
    const float* bf0   = (const float*)d_in[4];
    const float* Wb0   = (const float*)d_in[5];
    const float* bb0   = (const float*)d_in[6];
    const float* Wf1   = (const float*)d_in[7];
    const float* bf1   = (const float*)d_in[8];
    const float* Wb1   = (const float*)d_in[9];
    const float* bb1   = (const float*)d_in[10];
    float* out = (float*)d_out;

    float* buf = nullptr;
    cudaGetSymbolAddress((void**)&buf, g_buf);

    static cudaStream_t strm[3];
    static cudaEvent_t evFork, evJoin[3];
    static bool inited = false;
    if (!inited) {
        for (int i = 0; i < 3; i++)
            cudaStreamCreateWithFlags(&strm[i], cudaStreamNonBlocking);
        cudaEventCreateWithFlags(&evFork, cudaEventDisableTiming);
        for (int i = 0; i < 3; i++)
            cudaEventCreateWithFlags(&evJoin[i], cudaEventDisableTiming);
        inited = true;
    }

    zero_kernel<<<(unsigned)((STATE_TOTAL + 255) / 256), 256>>>(buf, STATE_TOTAL);
    {
        const int t0 = (int)(WT0_SZ / 2), t1 = (int)(WT1_SZ / 2);
        transpose_weights<64><<<(t0 + 255) / 256, 256>>>(Wf0, buf + OFF_WTF0);
        transpose_weights<64><<<(t0 + 255) / 256, 256>>>(Wb0, buf + OFF_WTB0);
        transpose_weights<128><<<(t1 + 255) / 256, 256>>>(Wf1, buf + OFF_WTF1);
        transpose_weights<128><<<(t1 + 255) / 256, 256>>>(Wb1, buf + OFF_WTB1);
    }
    cudaEventRecord(evFork, 0);
    for (int i = 0; i < 3; i++) cudaStreamWaitEvent(strm[i], evFork, 0);

    const int T = 16, B = 8;
    const size_t f0step = (size_t)B * 64 * 64 * 64;
    const size_t f1step = (size_t)B * 128 * 32 * 32;
    const dim3 grid0(16, 64 / 16, 8);
    const dim3 grid1(4, 128 / 16, 8);

    float* hf0[2] = { buf + OFF_HF0A, buf + OFF_HF0B };
    float* hb0[2] = { buf + OFF_HB0A, buf + OFF_HB0B };
    float* hf1[2] = { buf + OFF_HF1A, buf + OFF_HF1B };
    float* hb1[2] = { buf + OFF_HB1A, buf + OFF_HB1B };

    for (int t = 0; t < T; ++t) {
        const int p = t & 1, q = p ^ 1;
        convlstm_step<64, 64, 64><<<grid0, 256>>>(
            feat0 + (size_t)t * f0step, hf0[p], hf0[q], buf + OFF_CF0,
            buf + OFF_WTF0, bf0, mask + t * B);
    }
    for (int t = 0; t < T; ++t) {
        const int p = t & 1, q = p ^ 1;
        convlstm_step<64, 64, 64><<<grid0, 256, 0, strm[0]>>>(
            feat0 + (size_t)t * f0step, hb0[p], hb0[q], buf + OFF_CB0,
            buf + OFF_WTB0, bb0, mask + t * B);
    }
    for (int t = 0; t < T; ++t) {
        const int p = t & 1, q = p ^ 1;
        convlstm_step<128, 32, 32><<<grid1, 256, 0, strm[1]>>>(
            feat1 + (size_t)t * f1step, hf1[p], hf1[q], buf + OFF_CF1,
            buf + OFF_WTF1, bf1, mask + t * B);
    }
    for (int t = 0; t < T; ++t) {
        const int p = t & 1, q = p ^ 1;
        convlstm_step<128, 32, 32><<<grid1, 256, 0, strm[2]>>>(
            feat1 + (size_t)t * f1step, hb1[p], hb1[q], buf + OFF_CB1,
            buf + OFF_WTB1, bb1, mask + t * B);
    }

    for (int i = 0; i < 3; i++) {
        cudaEventRecord(evJoin[i], strm[i]);
        cudaStreamWaitEvent(0, evJoin[i], 0);
    }

    // T=16 even: final states are in the 'A' buffers.
    avg_kernel<<<(unsigned)((ST0 + 255) / 256), 256>>>(hf0[0], hb0[0], out, ST0);
    avg_kernel<<<(unsigned)((ST1 + 255) / 256), 256>>>(hf1[0], hb1[0], out + ST0, ST1);
}

// round 9
// speedup vs baseline: 3.5637x; 1.0048x over previous
#include <cuda_runtime.h>
#include <cstdint>
#include <math.h>

// ---------------------------------------------------------------------------
// Scratch: states + transposed pair-splatted weights (float buffer),
// and precomputed x-gates blobs (u64 buffer, register-layout).
// ---------------------------------------------------------------------------
#define ST0 2097152ull   // 8*64*64*64
#define ST1 1048576ull   // 8*128*32*32
#define WT0_SZ (2ull * 72 * 64 * 64)
#define WT1_SZ (2ull * 72 * 128 * 128)

#define OFF_HF0A 0ull
#define OFF_HF0B (OFF_HF0A + ST0)
#define OFF_CF0  (OFF_HF0B + ST0)
#define OFF_HB0A (OFF_CF0  + ST0)
#define OFF_HB0B (OFF_HB0A + ST0)
#define OFF_CB0  (OFF_HB0B + ST0)
#define OFF_HF1A (OFF_CB0  + ST0)
#define OFF_HF1B (OFF_HF1A + ST1)
#define OFF_CF1  (OFF_HF1B + ST1)
#define OFF_HB1A (OFF_CF1  + ST1)
#define OFF_HB1B (OFF_HB1A + ST1)
#define OFF_CB1  (OFF_HB1B + ST1)
#define OFF_WTF0 (OFF_CB1  + ST1)
#define OFF_WTB0 (OFF_WTF0 + WT0_SZ)
#define OFF_WTF1 (OFF_WTB0 + WT0_SZ)
#define OFF_WTB1 (OFF_WTF1 + WT1_SZ)
#define BUF_TOTAL (OFF_WTB1 + WT1_SZ)

__device__ float g_buf[BUF_TOTAL];
#define STATE_TOTAL (OFF_WTF0)

// x-gates blobs: per CTA 8192 u64 (64 outputs x 256 pixels), layout
// blob[(((k*2+r)*2+cp)<<8) + tid].
// level0 cell: 128z*4g*16tile*8192 = 67,108,864 u64 (512MiB)
// level1 cell: 128z*8g* 4tile*8192 = 33,554,432 u64 (256MiB)
#define XG0_CELL 67108864ull
#define XG1_CELL 33554432ull
#define XG_F0 0ull
#define XG_B0 (XG_F0 + XG0_CELL)
#define XG_F1 (XG_B0 + XG0_CELL)
#define XG_B1 (XG_F1 + XG1_CELL)
#define XG_TOTAL (XG_B1 + XG1_CELL)

__device__ unsigned long long g_xg[XG_TOTAL];

__global__ void zero_kernel(float* __restrict__ p, size_t n) {
    size_t i = (size_t)blockIdx.x * blockDim.x + threadIdx.x;
    if (i < n) p[i] = 0.0f;
}

// ---------------------------------------------------------------------------
// Weight transpose with (w,w) pair splat:
//   WT2 pair index (((g*2C + ci)*64 + o)*9 + tap); row(o,g)=(o>>4)*C+g*16+(o&15)
// ---------------------------------------------------------------------------
template<int C>
__global__ void transpose_weights(const float* __restrict__ W, float* __restrict__ WT2)
{
    const int total = (C / 16) * 2 * C * 64 * 9;
    int i = blockIdx.x * 256 + threadIdx.x;
    if (i >= total) return;
    int tap = i % 9;
    int r = i / 9;
    int o = r % 64; r /= 64;
    int ci = r % (2 * C);
    int g = r / (2 * C);
    int row = (o >> 4) * C + g * 16 + (o & 15);
    float w = W[((size_t)row * (2 * C) + ci) * 9 + tap];
    reinterpret_cast<float2*>(WT2)[i] = make_float2(w, w);
}

// ---------------------------------------------------------------------------
// helpers
// ---------------------------------------------------------------------------
__device__ __forceinline__ void cpa16(unsigned int dst, const float* src) {
    asm volatile("cp.async.cg.shared.global [%0], [%1], 16;" :: "r"(dst), "l"(src));
}
__device__ __forceinline__ void cpa4z(unsigned int dst, const float* src, bool v) {
    int sz = v ? 4 : 0;
    asm volatile("cp.async.ca.shared.global [%0], [%1], 4, %2;"
                 :: "r"(dst), "l"(src), "r"(sz));
}
__device__ __forceinline__ void cpa_commit() {
    asm volatile("cp.async.commit_group;" ::: "memory");
}
__device__ __forceinline__ unsigned long long pack2(float lo, float hi) {
    unsigned long long r;
    asm("mov.b64 %0, {%1, %2};" : "=l"(r) : "f"(lo), "f"(hi));
    return r;
}
__device__ __forceinline__ void fma2(unsigned long long& d,
                                     unsigned long long a, unsigned long long b) {
    asm("fma.rn.f32x2 %0, %1, %2, %0;" : "+l"(d) : "l"(a), "l"(b));
}
__device__ __forceinline__ void unpack2(unsigned long long v, float& lo, float& hi) {
    asm("mov.b64 {%0, %1}, %2;" : "=f"(lo), "=f"(hi) : "l"(v));
}

#define TSP 16
#define CI_BLK 4

// ---------------------------------------------------------------------------
// Precompute kernel: xgates = W_x (x) x for ALL (t,b) in one launch.
// grid: (tiles, C/16, T*B); z = t*8+b. Mask-skipped per z.
// ---------------------------------------------------------------------------
template<int C, int H, int W>
__global__ __launch_bounds__(256, 2)
void conv_x_pre(const float* __restrict__ feat,       // [T*B,C,H,W]
                const float* __restrict__ WT2,
                unsigned long long* __restrict__ xg,  // cell blob base
                const int* __restrict__ mask)         // [T*B]
{
    const int z = blockIdx.z;
    if (mask[z] <= 0) return;
    const int coGrp = blockIdx.y;
    const int tilesX = W / TSP;
    const int nTiles = (H / TSP) * tilesX;
    const int tileY  = (blockIdx.x / tilesX) * TSP;
    const int tileX  = (blockIdx.x % tilesX) * TSP;
    const int tid  = threadIdx.x;
    const int ty   = tid >> 5;
    const int lane = tid & 31;
    const int rp   = lane >> 2;
    const int cq   = lane & 3;

    __shared__ __align__(16) float sIn[2][CI_BLK][342];
    __shared__ __align__(16) float sW[2][CI_BLK * 1152];
    const unsigned int sInAddr = (unsigned int)__cvta_generic_to_shared(&sIn[0][0][0]);
    const unsigned int sWAddr  = (unsigned int)__cvta_generic_to_shared(&sW[0][0]);

    unsigned long long acc2[8][2][2];
    #pragma unroll
    for (int k = 0; k < 8; k++)
        #pragma unroll
        for (int r = 0; r < 2; r++)
            #pragma unroll
            for (int cc = 0; cc < 2; cc++)
                acc2[k][r][cc] = 0ull;

    const float* xb = feat + (size_t)z * C * H * W;
    const int NBLK = C / CI_BLK;

    auto stage = [&](int ci0s, int dbuf) {
        for (int i = tid; i < CI_BLK * 324; i += 256) {
            const int ciL = i / 324;
            const int rem = i - ciL * 324;
            const int r = rem / 18, cc = rem - r * 18;
            const float* srcp = xb + (size_t)(ci0s + ciL) * H * W;
            const int gy = tileY - 1 + r;
            const int gx = tileX - 1 + cc;
            const bool v = (gy >= 0 && gy < H && gx >= 0 && gx < W);
            const float* sp = v ? (srcp + gy * W + gx) : srcp;
            cpa4z(sInAddr + (unsigned int)(((dbuf * CI_BLK + ciL) * 342 + r * 19 + cc) * 4),
                  sp, v);
        }
        const float* wsrc = WT2 + ((size_t)(coGrp * 2 * C + ci0s)) * 1152;  // x-part rows
        for (int i = tid; i < (CI_BLK * 1152) / 4; i += 256) {
            cpa16(sWAddr + (unsigned int)((dbuf * CI_BLK * 1152 + i * 4) * 4), wsrc + i * 4);
        }
        cpa_commit();
    };

    stage(0, 0);
    for (int blk = 0; blk < NBLK; ++blk) {
        const int cur = blk & 1;
        if (blk + 1 < NBLK) {
            stage((blk + 1) * CI_BLK, cur ^ 1);
            asm volatile("cp.async.wait_group 1;" ::: "memory");
        } else {
            asm volatile("cp.async.wait_group 0;" ::: "memory");
        }
        __syncthreads();

        #pragma unroll
        for (int ciL = 0; ciL < CI_BLK; ciL++) {
            unsigned long long xp[4][5];
            #pragma unroll
            for (int i = 0; i < 4; i++) {
                float xs[6];
                #pragma unroll
                for (int j = 0; j < 6; j++)
                    xs[j] = sIn[cur][ciL][(2 * rp + i) * 19 + (4 * cq + j)];
                #pragma unroll
                for (int j = 0; j < 5; j++)
                    xp[i][j] = pack2(xs[j], xs[j + 1]);
            }
            const unsigned long long* wci =
                reinterpret_cast<const unsigned long long*>(&sW[cur][ciL * 1152]);
            #pragma unroll
            for (int tap = 0; tap < 9; tap++) {
                const int ky = tap / 3, kx = tap % 3;
                #pragma unroll
                for (int k = 0; k < 8; k++) {
                    const unsigned long long w2 = wci[(k * 8 + ty) * 9 + tap];
                    fma2(acc2[k][0][0], xp[ky][kx],     w2);
                    fma2(acc2[k][0][1], xp[ky][kx + 2], w2);
                    fma2(acc2[k][1][0], xp[ky + 1][kx],     w2);
                    fma2(acc2[k][1][1], xp[ky + 1][kx + 2], w2);
                }
            }
        }
        __syncthreads();
    }

    unsigned long long* blob = xg +
        (((size_t)z * (C / 16) + coGrp) * nTiles + blockIdx.x) * 8192;
    #pragma unroll
    for (int k = 0; k < 8; k++)
        #pragma unroll
        for (int r = 0; r < 2; r++)
            #pragma unroll
            for (int cp = 0; cp < 2; cp++)
                blob[((((k * 2 + r) * 2 + cp) << 8) + tid)] = acc2[k][r][cp];
}

// ---------------------------------------------------------------------------
// Recurrent kernel: h-part conv (C channels) + xgate + bias + LSTM update.
// ---------------------------------------------------------------------------
template<int C, int H, int W>
__global__ __launch_bounds__(256, 2)
void convlstm_step(const float* __restrict__ h_in,
                   float* __restrict__ h_out,
                   float* __restrict__ c,
                   const float* __restrict__ WT2, const float* __restrict__ bias,
                   const unsigned long long* __restrict__ xg,
                   const int* __restrict__ mask_t, int t)
{
    const int b = blockIdx.z;
    const int coGrp = blockIdx.y;
    const int coBase = coGrp * 16;
    const int tilesX = W / TSP;
    const int nTiles = (H / TSP) * tilesX;
    const int tileY  = (blockIdx.x / tilesX) * TSP;
    const int tileX  = (blockIdx.x % tilesX) * TSP;
    const int tid  = threadIdx.x;

    if (mask_t[b] <= 0) {
        for (int i = tid; i < 16 * TSP * TSP; i += 256) {
            const int chL = i >> 8;
            const int rem = i & 255;
            const int y = tileY + (rem >> 4);
            const int xx = tileX + (rem & 15);
            const size_t idx = ((size_t)b * C + coBase + chL) * (size_t)(H * W)
                             + (size_t)y * W + xx;
            h_out[idx] = h_in[idx];
        }
        return;
    }

    const int ty   = tid >> 5;
    const int lane = tid & 31;
    const int rp   = lane >> 2;
    const int cq   = lane & 3;

    __shared__ __align__(16) float sIn[2][CI_BLK][342];
    __shared__ __align__(16) float sW[2][CI_BLK * 1152];
    const unsigned int sInAddr = (unsigned int)__cvta_generic_to_shared(&sIn[0][0][0]);
    const unsigned int sWAddr  = (unsigned int)__cvta_generic_to_shared(&sW[0][0]);

    unsigned long long acc2[8][2][2];
    #pragma unroll
    for (int k = 0; k < 8; k++)
        #pragma unroll
        for (int r = 0; r < 2; r++)
            #pragma unroll
            for (int cc = 0; cc < 2; cc++)
                acc2[k][r][cc] = 0ull;

    const float* hb = h_in + (size_t)b * C * H * W;
    const int NBLK = C / CI_BLK;

    auto stage = [&](int ci0s, int dbuf) {
        for (int i = tid; i < CI_BLK * 324; i += 256) {
            const int ciL = i / 324;
            const int rem = i - ciL * 324;
            const int r = rem / 18, cc = rem - r * 18;
            const float* srcp = hb + (size_t)(ci0s + ciL) * H * W;
            const int gy = tileY - 1 + r;
            const int gx = tileX - 1 + cc;
            const bool v = (gy >= 0 && gy < H && gx >= 0 && gx < W);
            const float* sp = v ? (srcp + gy * W + gx) : srcp;
            cpa4z(sInAddr + (unsigned int)(((dbuf * CI_BLK + ciL) * 342 + r * 19 + cc) * 4),
                  sp, v);
        }
        // h-part weight rows: ci index C + ci0s
        const float* wsrc = WT2 + ((size_t)(coGrp * 2 * C + C + ci0s)) * 1152;
        for (int i = tid; i < (CI_BLK * 1152) / 4; i += 256) {
            cpa16(sWAddr + (unsigned int)((dbuf * CI_BLK * 1152 + i * 4) * 4), wsrc + i * 4);
        }
        cpa_commit();
    };

    stage(0, 0);
    for (int blk = 0; blk < NBLK; ++blk) {
        const int cur = blk & 1;
        if (blk + 1 < NBLK) {
            stage((blk + 1) * CI_BLK, cur ^ 1);
            asm volatile("cp.async.wait_group 1;" ::: "memory");
        } else {
            asm volatile("cp.async.wait_group 0;" ::: "memory");
        }
        __syncthreads();

        #pragma unroll
        for (int ciL = 0; ciL < CI_BLK; ciL++) {
            unsigned long long xp[4][5];
            #pragma unroll
            for (int i = 0; i < 4; i++) {
                float xs[6];
                #pragma unroll
                for (int j = 0; j < 6; j++)
                    xs[j] = sIn[cur][ciL][(2 * rp + i) * 19 + (4 * cq + j)];
                #pragma unroll
                for (int j = 0; j < 5; j++)
                    xp[i][j] = pack2(xs[j], xs[j + 1]);
            }
            const unsigned long long* wci =
                reinterpret_cast<const unsigned long long*>(&sW[cur][ciL * 1152]);
            #pragma unroll
            for (int tap = 0; tap < 9; tap++) {
                const int ky = tap / 3, kx = tap % 3;
                #pragma unroll
                for (int k = 0; k < 8; k++) {
                    const unsigned long long w2 = wci[(k * 8 + ty) * 9 + tap];
                    fma2(acc2[k][0][0], xp[ky][kx],     w2);
                    fma2(acc2[k][0][1], xp[ky][kx + 2], w2);
                    fma2(acc2[k][1][0], xp[ky + 1][kx],     w2);
                    fma2(acc2[k][1][1], xp[ky + 1][kx + 2], w2);
                }
            }
        }
        __syncthreads();
    }

    // ---- epilogue: add precomputed xgate + bias, LSTM update ----
    const int z = t * 8 + b;
    const unsigned long long* blob = xg +
        (((size_t)z * (C / 16) + coGrp) * nTiles + blockIdx.x) * 8192;

    #pragma unroll
    for (int j = 0; j < 2; j++) {
        const int ch = coBase + j * 8 + ty;
        const float bi = bias[0 * C + ch];
        const float bf = bias[1 * C + ch];
        const float bo = bias[2 * C + ch];
        const float bg = bias[3 * C + ch];
        #pragma unroll
        for (int r = 0; r < 2; r++) {
            const int y = tileY + 2 * rp + r;
            #pragma unroll
            for (int cp = 0; cp < 2; cp++) {
                float a_i[2], a_f[2], a_o[2], a_g[2];
                float x_i[2], x_f[2], x_o[2], x_g[2];
                unpack2(acc2[0 + j][r][cp], a_i[0], a_i[1]);
                unpack2(acc2[2 + j][r][cp], a_f[0], a_f[1]);
                unpack2(acc2[4 + j][r][cp], a_o[0], a_o[1]);
                unpack2(acc2[6 + j][r][cp], a_g[0], a_g[1]);
                unpack2(blob[((((0 + j) * 2 + r) * 2 + cp) << 8) + tid], x_i[0], x_i[1]);
                unpack2(blob[((((2 + j) * 2 + r) * 2 + cp) << 8) + tid], x_f[0], x_f[1]);
                unpack2(blob[((((4 + j) * 2 + r) * 2 + cp) << 8) + tid], x_o[0], x_o[1]);
                unpack2(blob[((((6 + j) * 2 + r) * 2 + cp) << 8) + tid], x_g[0], x_g[1]);
                #pragma unroll
                for (int u = 0; u < 2; u++) {
                    const int xx = tileX + 4 * cq + cp * 2 + u;
                    const size_t idx = ((size_t)b * C + ch) * (size_t)(H * W)
                                     + (size_t)y * W + xx;
                    const float gi = a_i[u] + x_i[u] + bi;
                    const float gf = a_f[u] + x_f[u] + bf;
                    const float go = a_o[u] + x_o[u] + bo;
                    const float gg = a_g[u] + x_g[u] + bg;
                    const float si = 1.0f / (1.0f + __expf(-gi));
                    const float sf = 1.0f / (1.0f + __expf(-gf));
                    const float so = 1.0f / (1.0f + __expf(-go));
                    const float tg = tanhf(gg);
                    const float cn = sf * c[idx] + si * tg;
                    c[idx] = cn;
                    h_out[idx] = so * tanhf(cn);
                }
            }
        }
    }
}

__global__ void avg_kernel(const float* __restrict__ a, const float* __restrict__ b,
                           float* __restrict__ out, size_t n)
{
    size_t i = (size_t)blockIdx.x * blockDim.x + threadIdx.x;
    if (i < n) out[i] = 0.5f * (a[i] + b[i]);
}

// ---------------------------------------------------------------------------
// Launch: per cell stream = [one big x-precompute launch] then [16 recurrent
// steps]. 4 streams total (default + 3), same resource budget as the passing
// round-7 config.
// ---------------------------------------------------------------------------
extern "C" void kernel_launch(void* const* d_in, const int* in_sizes, int n_in,
                              void* d_out, int out_size)
{
    const float* feat0 = (const float*)d_in[0];
    const float* feat1 = (const float*)d_in[1];
    const int*   mask  = (const int*)  d_in[2];
    const float* Wf0   = (const float*)d_in[3];
    const float* bf0   = (const float*)d_in[4];
    const float* Wb0   = (const float*)d_in[5];
    const float* bb0   = (const float*)d_in[6];
    const float* Wf1   = (const float*)d_in[7];
    const float* bf1   = (const float*)d_in[8];
    const float* Wb1   = (const float*)d_in[9];
    const float* bb1   = (const float*)d_in[10];
    float* out = (float*)d_out;

    float* buf = nullptr;
    cudaGetSymbolAddress((void**)&buf, g_buf);
    unsigned long long* xg = nullptr;
    cudaGetSymbolAddress((void**)&xg, g_xg);

    static cudaStream_t strm[3];
    static cudaEvent_t evFork, evJoin[3];
    static bool inited = false;
    if (!inited) {
        for (int i = 0; i < 3; i++)
            cudaStreamCreateWithFlags(&strm[i], cudaStreamNonBlocking);
        cudaEventCreateWithFlags(&evFork, cudaEventDisableTiming);
        for (int i = 0; i < 3; i++)
            cudaEventCreateWithFlags(&evJoin[i], cudaEventDisableTiming);
        inited = true;
    }

    zero_kernel<<<(unsigned)((STATE_TOTAL + 255) / 256), 256>>>(buf, STATE_TOTAL);
    {
        const int t0 = (int)(WT0_SZ / 2), t1 = (int)(WT1_SZ / 2);
        transpose_weights<64><<<(t0 + 255) / 256, 256>>>(Wf0, buf + OFF_WTF0);
        transpose_weights<64><<<(t0 + 255) / 256, 256>>>(Wb0, buf + OFF_WTB0);
        transpose_weights<128><<<(t1 + 255) / 256, 256>>>(Wf1, buf + OFF_WTF1);
        transpose_weights<128><<<(t1 + 255) / 256, 256>>>(Wb1, buf + OFF_WTB1);
    }
    cudaEventRecord(evFork, 0);
    for (int i = 0; i < 3; i++) cudaStreamWaitEvent(strm[i], evFork, 0);

    const int T = 16, B = 8;
    const dim3 gridPre0(16, 4, T * B);   // 8192 CTAs
    const dim3 gridPre1(4, 8, T * B);    // 4096 CTAs
    const dim3 grid0(16, 4, B);
    const dim3 grid1(4, 8, B);

    const float* WTs[4] = { buf + OFF_WTF0, buf + OFF_WTB0, buf + OFF_WTF1, buf + OFF_WTB1 };
    unsigned long long* XGs[4] = { xg + XG_F0, xg + XG_B0, xg + XG_F1, xg + XG_B1 };

    // phase 1: one big precompute launch per cell (stream-ordered before phase 2)
    conv_x_pre<64, 64, 64><<<gridPre0, 256>>>(feat0, WTs[0], XGs[0], mask);
    conv_x_pre<64, 64, 64><<<gridPre0, 256, 0, strm[0]>>>(feat0, WTs[1], XGs[1], mask);
    conv_x_pre<128, 32, 32><<<gridPre1, 256, 0, strm[1]>>>(feat1, WTs[2], XGs[2], mask);
    conv_x_pre<128, 32, 32><<<gridPre1, 256, 0, strm[2]>>>(feat1, WTs[3], XGs[3], mask);

    float* hf0[2] = { buf + OFF_HF0A, buf + OFF_HF0B };
    float* hb0[2] = { buf + OFF_HB0A, buf + OFF_HB0B };
    float* hf1[2] = { buf + OFF_HF1A, buf + OFF_HF1B };
    float* hb1[2] = { buf + OFF_HB1A, buf + OFF_HB1B };

    // phase 2: recurrent chains (h-part conv only)
    for (int t = 0; t < T; ++t) {
        const int p = t & 1, q = p ^ 1;
        convlstm_step<64, 64, 64><<<grid0, 256>>>(
            hf0[p], hf0[q], buf + OFF_CF0, WTs[0], bf0, XGs[0], mask + t * B, t);
    }
    for (int t = 0; t < T; ++t) {
        const int p = t & 1, q = p ^ 1;
        convlstm_step<64, 64, 64><<<grid0, 256, 0, strm[0]>>>(
            hb0[p], hb0[q], buf + OFF_CB0, WTs[1], bb0, XGs[1], mask + t * B, t);
    }
    for (int t = 0; t < T; ++t) {
        const int p = t & 1, q = p ^ 1;
        convlstm_step<128, 32, 32><<<grid1, 256, 0, strm[1]>>>(
            hf1[p], hf1[q], buf + OFF_CF1, WTs[2], bf1, XGs[2], mask + t * B, t);
    }
    for (int t = 0; t < T; ++t) {
        const int p = t & 1, q = p ^ 1;
        convlstm_step<128, 32, 32><<<grid1, 256, 0, strm[2]>>>(
            hb1[p], hb1[q], buf + OFF_CB1, WTs[3], bb1, XGs[3], mask + t * B, t);
    }

    for (int i = 0; i < 3; i++) {
        cudaEventRecord(evJoin[i], strm[i]);
        cudaStreamWaitEvent(0, evJoin[i], 0);
    }

    avg_kernel<<<(unsigned)((ST0 + 255) / 256), 256>>>(hf0[0], hb0[0], out, ST0);
    avg_kernel<<<(unsigned)((ST1 + 255) / 256), 256>>>(hf1[0], hb1[0], out + ST0, ST1);
}

// round 10
// speedup vs baseline: 3.5831x; 1.0054x over previous
#include <cuda_runtime.h>
#include <cstdint>
#include <math.h>

// ---------------------------------------------------------------------------
// Scratch: states + transposed pair-splatted weights + x-gates blobs.
// ---------------------------------------------------------------------------
#define ST0 2097152ull   // 8*64*64*64
#define ST1 1048576ull   // 8*128*32*32
#define WT0_SZ (2ull * 72 * 64 * 64)
#define WT1_SZ (2ull * 72 * 128 * 128)

#define OFF_HF0A 0ull
#define OFF_HF0B (OFF_HF0A + ST0)
#define OFF_CF0  (OFF_HF0B + ST0)
#define OFF_HB0A (OFF_CF0  + ST0)
#define OFF_HB0B (OFF_HB0A + ST0)
#define OFF_CB0  (OFF_HB0B + ST0)
#define OFF_HF1A (OFF_CB0  + ST0)
#define OFF_HF1B (OFF_HF1A + ST1)
#define OFF_CF1  (OFF_HF1B + ST1)
#define OFF_HB1A (OFF_CF1  + ST1)
#define OFF_HB1B (OFF_HB1A + ST1)
#define OFF_CB1  (OFF_HB1B + ST1)
#define OFF_WTF0 (OFF_CB1  + ST1)
#define OFF_WTB0 (OFF_WTF0 + WT0_SZ)
#define OFF_WTF1 (OFF_WTB0 + WT0_SZ)
#define OFF_WTB1 (OFF_WTF1 + WT1_SZ)
#define BUF_TOTAL (OFF_WTB1 + WT1_SZ)

__device__ float g_buf[BUF_TOTAL];
#define STATE_TOTAL (OFF_WTF0)

#define XG0_CELL 67108864ull
#define XG1_CELL 33554432ull
#define XG_F0 0ull
#define XG_B0 (XG_F0 + XG0_CELL)
#define XG_F1 (XG_B0 + XG0_CELL)
#define XG_B1 (XG_F1 + XG1_CELL)
#define XG_TOTAL (XG_B1 + XG1_CELL)

__device__ unsigned long long g_xg[XG_TOTAL];

__global__ void zero_kernel(float* __restrict__ p, size_t n) {
    size_t i = (size_t)blockIdx.x * blockDim.x + threadIdx.x;
    if (i < n) p[i] = 0.0f;
}

// ---------------------------------------------------------------------------
// ONE merged weight transpose for all 4 cells (keeps prelude to 2 launches so
// ncu -s 5 lands on a real conv kernel).
// ---------------------------------------------------------------------------
__global__ void transpose_all(const float* __restrict__ W0f, const float* __restrict__ W0b,
                              const float* __restrict__ W1f, const float* __restrict__ W1b,
                              float* __restrict__ o0f, float* __restrict__ o0b,
                              float* __restrict__ o1f, float* __restrict__ o1b)
{
    const int t0 = 294912, t1 = 1179648;
    int j = blockIdx.x * 256 + threadIdx.x;
    const float* W; float* O; int C;
    if (j < t0)              { W = W0f; O = o0f; C = 64; }
    else if ((j -= t0) < t0) { W = W0b; O = o0b; C = 64; }
    else if ((j -= t0) < t1) { W = W1f; O = o1f; C = 128; }
    else if ((j -= t1) < t1) { W = W1b; O = o1b; C = 128; }
    else return;
    int tap = j % 9;
    int r = j / 9;
    int o = r % 64; r /= 64;
    int ci = r % (2 * C);
    int g = r / (2 * C);
    int row = (o >> 4) * C + g * 16 + (o & 15);
    float w = W[((size_t)row * (2 * C) + ci) * 9 + tap];
    reinterpret_cast<float2*>(O)[j] = make_float2(w, w);
}

// ---------------------------------------------------------------------------
// helpers
// ---------------------------------------------------------------------------
__device__ __forceinline__ void cpa16(unsigned int dst, const float* src) {
    asm volatile("cp.async.cg.shared.global [%0], [%1], 16;" :: "r"(dst), "l"(src));
}
__device__ __forceinline__ void cpa16z(unsigned int dst, const float* src, bool v) {
    int sz = v ? 16 : 0;
    asm volatile("cp.async.cg.shared.global [%0], [%1], 16, %2;"
                 :: "r"(dst), "l"(src), "r"(sz));
}
__device__ __forceinline__ void cpa_commit() {
    asm volatile("cp.async.commit_group;" ::: "memory");
}
__device__ __forceinline__ unsigned long long pack2(float lo, float hi) {
    unsigned long long r;
    asm("mov.b64 %0, {%1, %2};" : "=l"(r) : "f"(lo), "f"(hi));
    return r;
}
__device__ __forceinline__ void fma2(unsigned long long& d,
                                     unsigned long long a, unsigned long long b) {
    asm("fma.rn.f32x2 %0, %1, %2, %0;" : "+l"(d) : "l"(a), "l"(b));
}
__device__ __forceinline__ void unpack2(unsigned long long v, float& lo, float& hi) {
    asm("mov.b64 {%0, %1}, %2;" : "=f"(lo), "=f"(hi) : "l"(v));
}

#define TSP 16
#define CI_BLK 8
// input row: 28 floats covering global cols [tileX-4, tileX+23]; chunks 0..5 used
#define SIN_ROW 28
#define SIN_CI (18 * SIN_ROW)              // 504 floats per ci
#define SIN_BUF (CI_BLK * SIN_CI)          // 4032 floats per buffer
#define SW_BUF (CI_BLK * 1152)             // 9216 floats per buffer
#define SMEM_BYTES ((2 * SIN_BUF + 2 * SW_BUF) * 4)   // 105984 B

// ---------------------------------------------------------------------------
// Shared conv core: accumulates 64 outputs x 256 pixels over nCi channels of
// `base` using weight rows starting at wbase. acc2 in caller registers.
// ---------------------------------------------------------------------------
template<int H, int W>
__device__ __forceinline__ void conv_core(
    const float* __restrict__ base, const float* __restrict__ wbase,
    int nCi, int tileY, int tileX, int tid, int ty, int rp, int cq,
    float* sInF, float* sWF, unsigned int sInAddr, unsigned int sWAddr,
    unsigned long long (&acc2)[8][2][2])
{
    const int NBLK = nCi / CI_BLK;

    auto stage = [&](int ci0s, int dbuf) {
        // inputs: CI_BLK x 18 rows x 6 chunks of 16B
        for (int i = tid; i < CI_BLK * 108; i += 256) {
            const int ciL = i / 108;
            const int rem = i - ciL * 108;
            const int r = rem / 6, k = rem - r * 6;
            const float* srcp = base + (size_t)(ci0s + ciL) * H * W;
            const int gy = tileY - 1 + r;
            const bool vrow = (gy >= 0 && gy < H);
            const bool vcol = (k == 0) ? (tileX > 0)
                            : ((k < 5) ? true : (tileX + 16 < W));
            const bool v = vrow && vcol;
            const float* sp = srcp + (v ? (gy * W + tileX - 4 + 4 * k) : 0);
            cpa16z(sInAddr + (unsigned int)((((dbuf * CI_BLK + ciL) * SIN_CI)
                                             + r * SIN_ROW + 4 * k) * 4), sp, v);
        }
        // weights: CI_BLK*1152 contiguous floats (pairs), 16B chunks
        const float* wsrc = wbase + (size_t)ci0s * 1152;
        for (int i = tid; i < (CI_BLK * 1152) / 4; i += 256) {
            cpa16(sWAddr + (unsigned int)((dbuf * SW_BUF + i * 4) * 4), wsrc + i * 4);
        }
        cpa_commit();
    };

    stage(0, 0);
    for (int blk = 0; blk < NBLK; ++blk) {
        const int cur = blk & 1;
        if (blk + 1 < NBLK) {
            stage((blk + 1) * CI_BLK, cur ^ 1);
            asm volatile("cp.async.wait_group 1;" ::: "memory");
        } else {
            asm volatile("cp.async.wait_group 0;" ::: "memory");
        }
        __syncthreads();

        #pragma unroll 4
        for (int ciL = 0; ciL < CI_BLK; ciL++) {
            unsigned long long xp[4][5];
            const float* sci = sInF + (cur * CI_BLK + ciL) * SIN_CI;
            #pragma unroll
            for (int i = 0; i < 4; i++) {
                float xs[6];
                #pragma unroll
                for (int j = 0; j < 6; j++)
                    xs[j] = sci[(2 * rp + i) * SIN_ROW + 3 + 4 * cq + j];
                #pragma unroll
                for (int j = 0; j < 5; j++)
                    xp[i][j] = pack2(xs[j], xs[j + 1]);
            }
            const unsigned long long* wci = reinterpret_cast<const unsigned long long*>(
                sWF + (cur * SW_BUF + ciL * 1152));
            #pragma unroll
            for (int tap = 0; tap < 9; tap++) {
                const int ky = tap / 3, kx = tap % 3;
                #pragma unroll
                for (int k = 0; k < 8; k++) {
                    const unsigned long long w2 = wci[(k * 8 + ty) * 9 + tap];
                    fma2(acc2[k][0][0], xp[ky][kx],     w2);
                    fma2(acc2[k][0][1], xp[ky][kx + 2], w2);
                    fma2(acc2[k][1][0], xp[ky + 1][kx],     w2);
                    fma2(acc2[k][1][1], xp[ky + 1][kx + 2], w2);
                }
            }
        }
        __syncthreads();
    }
}

// ---------------------------------------------------------------------------
// Precompute: xgates = W_x (x) x for ALL (t,b). grid (tiles, C/16, T*B).
// ---------------------------------------------------------------------------
template<int C, int H, int W>
__global__ __launch_bounds__(256, 2)
void conv_x_pre(const float* __restrict__ feat,
                const float* __restrict__ WT2,
                unsigned long long* __restrict__ xg,
                const int* __restrict__ mask)
{
    const int z = blockIdx.z;
    if (mask[z] <= 0) return;
    const int coGrp = blockIdx.y;
    const int tilesX = W / TSP;
    const int nTiles = (H / TSP) * tilesX;
    const int tileY  = (blockIdx.x / tilesX) * TSP;
    const int tileX  = (blockIdx.x % tilesX) * TSP;
    const int tid  = threadIdx.x;
    const int ty   = tid >> 5;
    const int lane = tid & 31;
    const int rp   = lane >> 2;
    const int cq   = lane & 3;

    extern __shared__ float dsm[];
    float* sInF = dsm;
    float* sWF  = dsm + 2 * SIN_BUF;
    const unsigned int sInAddr = (unsigned int)__cvta_generic_to_shared(sInF);
    const unsigned int sWAddr  = (unsigned int)__cvta_generic_to_shared(sWF);

    unsigned long long acc2[8][2][2];
    #pragma unroll
    for (int k = 0; k < 8; k++)
        #pragma unroll
        for (int r = 0; r < 2; r++)
            #pragma unroll
            for (int cc = 0; cc < 2; cc++)
                acc2[k][r][cc] = 0ull;

    conv_core<H, W>(feat + (size_t)z * C * H * W,
                    WT2 + (size_t)(coGrp * 2 * C) * 1152,     // x-part rows
                    C, tileY, tileX, tid, ty, rp, cq,
                    sInF, sWF, sInAddr, sWAddr, acc2);

    unsigned long long* blob = xg +
        (((size_t)z * (C / 16) + coGrp) * nTiles + blockIdx.x) * 8192;
    #pragma unroll
    for (int k = 0; k < 8; k++)
        #pragma unroll
        for (int r = 0; r < 2; r++)
            #pragma unroll
            for (int cp = 0; cp < 2; cp++)
                blob[((((k * 2 + r) * 2 + cp) << 8) + tid)] = acc2[k][r][cp];
}

// ---------------------------------------------------------------------------
// Recurrent: h-part conv + xgate + bias + LSTM update.
// ---------------------------------------------------------------------------
template<int C, int H, int W>
__global__ __launch_bounds__(256, 2)
void convlstm_step(const float* __restrict__ h_in,
                   float* __restrict__ h_out,
                   float* __restrict__ c,
                   const float* __restrict__ WT2, const float* __restrict__ bias,
                   const unsigned long long* __restrict__ xg,
                   const int* __restrict__ mask_t, int t)
{
    const int b = blockIdx.z;
    const int coGrp = blockIdx.y;
    const int coBase = coGrp * 16;
    const int tilesX = W / TSP;
    const int nTiles = (H / TSP) * tilesX;
    const int tileY  = (blockIdx.x / tilesX) * TSP;
    const int tileX  = (blockIdx.x % tilesX) * TSP;
    const int tid  = threadIdx.x;

    if (mask_t[b] <= 0) {
        for (int i = tid; i < 16 * TSP * TSP; i += 256) {
            const int chL = i >> 8;
            const int rem = i & 255;
            const int y = tileY + (rem >> 4);
            const int xx = tileX + (rem & 15);
            const size_t idx = ((size_t)b * C + coBase + chL) * (size_t)(H * W)
                             + (size_t)y * W + xx;
            h_out[idx] = h_in[idx];
        }
        return;
    }

    const int ty   = tid >> 5;
    const int lane = tid & 31;
    const int rp   = lane >> 2;
    const int cq   = lane & 3;

    extern __shared__ float dsm[];
    float* sInF = dsm;
    float* sWF  = dsm + 2 * SIN_BUF;
    const unsigned int sInAddr = (unsigned int)__cvta_generic_to_shared(sInF);
    const unsigned int sWAddr  = (unsigned int)__cvta_generic_to_shared(sWF);

    unsigned long long acc2[8][2][2];
    #pragma unroll
    for (int k = 0; k < 8; k++)
        #pragma unroll
        for (int r = 0; r < 2; r++)
            #pragma unroll
            for (int cc = 0; cc < 2; cc++)
                acc2[k][r][cc] = 0ull;

    conv_core<H, W>(h_in + (size_t)b * C * H * W,
                    WT2 + (size_t)(coGrp * 2 * C + C) * 1152,  // h-part rows
                    C, tileY, tileX, tid, ty, rp, cq,
                    sInF, sWF, sInAddr, sWAddr, acc2);

    const int z = t * 8 + b;
    const unsigned long long* blob = xg +
        (((size_t)z * (C / 16) + coGrp) * nTiles + blockIdx.x) * 8192;

    #pragma unroll
    for (int j = 0; j < 2; j++) {
        const int ch = coBase + j * 8 + ty;
        const float bi = bias[0 * C + ch];
        const float bf = bias[1 * C + ch];
        const float bo = bias[2 * C + ch];
        const float bg = bias[3 * C + ch];
        #pragma unroll
        for (int r = 0; r < 2; r++) {
            const int y = tileY + 2 * rp + r;
            #pragma unroll
            for (int cp = 0; cp < 2; cp++) {
                float a_i[2], a_f[2], a_o[2], a_g[2];
                float x_i[2], x_f[2], x_o[2], x_g[2];
                unpack2(acc2[0 + j][r][cp], a_i[0], a_i[1]);
                unpack2(acc2[2 + j][r][cp], a_f[0], a_f[1]);
                unpack2(acc2[4 + j][r][cp], a_o[0], a_o[1]);
                unpack2(acc2[6 + j][r][cp], a_g[0], a_g[1]);
                unpack2(blob[((((0 + j) * 2 + r) * 2 + cp) << 8) + tid], x_i[0], x_i[1]);
                unpack2(blob[((((2 + j) * 2 + r) * 2 + cp) << 8) + tid], x_f[0], x_f[1]);
                unpack2(blob[((((4 + j) * 2 + r) * 2 + cp) << 8) + tid], x_o[0], x_o[1]);
                unpack2(blob[((((6 + j) * 2 + r) * 2 + cp) << 8) + tid], x_g[0], x_g[1]);
                #pragma unroll
                for (int u = 0; u < 2; u++) {
                    const int xx = tileX + 4 * cq + cp * 2 + u;
                    const size_t idx = ((size_t)b * C + ch) * (size_t)(H * W)
                                     + (size_t)y * W + xx;
                    const float gi = a_i[u] + x_i[u] + bi;
                    const float gf = a_f[u] + x_f[u] + bf;
                    const float go = a_o[u] + x_o[u] + bo;
                    const float gg = a_g[u] + x_g[u] + bg;
                    const float si = 1.0f / (1.0f + __expf(-gi));
                    const float sf = 1.0f / (1.0f + __expf(-gf));
                    const float so = 1.0f / (1.0f + __expf(-go));
                    const float tg = tanhf(gg);
                    const float cn = sf * c[idx] + si * tg;
                    c[idx] = cn;
                    h_out[idx] = so * tanhf(cn);
                }
            }
        }
    }
}

__global__ void avg_kernel(const float* __restrict__ a, const float* __restrict__ b,
                           float* __restrict__ out, size_t n)
{
    size_t i = (size_t)blockIdx.x * blockDim.x + threadIdx.x;
    if (i < n) out[i] = 0.5f * (a[i] + b[i]);
}

// ---------------------------------------------------------------------------
// Launch
// ---------------------------------------------------------------------------
extern "C" void kernel_launch(void* const* d_in, const int* in_sizes, int n_in,
                              void* d_out, int out_size)
{
    const float* feat0 = (const float*)d_in[0];
    const float* feat1 = (const float*)d_in[1];
    const int*   mask  = (const int*)  d_in[2];
    const float* Wf0   = (const float*)d_in[3];
    const float* bf0   = (const float*)d_in[4];
    const float* Wb0   = (const float*)d_in[5];
    const float* bb0   = (const float*)d_in[6];
    const float* Wf1   = (const float*)d_in[7];
    const float* bf1   = (const float*)d_in[8];
    const float* Wb1   = (const float*)d_in[9];
    const float* bb1   = (const float*)d_in[10];
    float* out = (float*)d_out;

    float* buf = nullptr;
    cudaGetSymbolAddress((void**)&buf, g_buf);
    unsigned long long* xg = nullptr;
    cudaGetSymbolAddress((void**)&xg, g_xg);

    static cudaStream_t strm[3];
    static cudaEvent_t evFork, evJoin[3];
    static bool inited = false;
    if (!inited) {
        for (int i = 0; i < 3; i++)
            cudaStreamCreateWithFlags(&strm[i], cudaStreamNonBlocking);
        cudaEventCreateWithFlags(&evFork, cudaEventDisableTiming);
        for (int i = 0; i < 3; i++)
            cudaEventCreateWithFlags(&evJoin[i], cudaEventDisableTiming);
        cudaFuncSetAttribute(conv_x_pre<64, 64, 64>,
            cudaFuncAttributeMaxDynamicSharedMemorySize, SMEM_BYTES);
        cudaFuncSetAttribute(conv_x_pre<128, 32, 32>,
            cudaFuncAttributeMaxDynamicSharedMemorySize, SMEM_BYTES);
        cudaFuncSetAttribute(convlstm_step<64, 64, 64>,
            cudaFuncAttributeMaxDynamicSharedMemorySize, SMEM_BYTES);
        cudaFuncSetAttribute(convlstm_step<128, 32, 32>,
            cudaFuncAttributeMaxDynamicSharedMemorySize, SMEM_BYTES);
        inited = true;
    }

    zero_kernel<<<(unsigned)((STATE_TOTAL + 255) / 256), 256>>>(buf, STATE_TOTAL);
    transpose_all<<<11520, 256>>>(Wf0, Wb0, Wf1, Wb1,
                                  buf + OFF_WTF0, buf + OFF_WTB0,
                                  buf + OFF_WTF1, buf + OFF_WTB1);
    cudaEventRecord(evFork, 0);
    for (int i = 0; i < 3; i++) cudaStreamWaitEvent(strm[i], evFork, 0);

    const int T = 16, B = 8;
    const dim3 gridPre0(16, 4, T * B);
    const dim3 gridPre1(4, 8, T * B);
    const dim3 grid0(16, 4, B);
    const dim3 grid1(4, 8, B);

    const float* WTs[4] = { buf + OFF_WTF0, buf + OFF_WTB0, buf + OFF_WTF1, buf + OFF_WTB1 };
    unsigned long long* XGs[4] = { xg + XG_F0, xg + XG_B0, xg + XG_F1, xg + XG_B1 };

    // phase 1: one big precompute launch per cell
    conv_x_pre<64, 64, 64><<<gridPre0, 256, SMEM_BYTES>>>(feat0, WTs[0], XGs[0], mask);
    conv_x_pre<64, 64, 64><<<gridPre0, 256, SMEM_BYTES, strm[0]>>>(feat0, WTs[1], XGs[1], mask);
    conv_x_pre<128, 32, 32><<<gridPre1, 256, SMEM_BYTES, strm[1]>>>(feat1, WTs[2], XGs[2], mask);
    conv_x_pre<128, 32, 32><<<gridPre1, 256, SMEM_BYTES, strm[2]>>>(feat1, WTs[3], XGs[3], mask);

    float* hf0[2] = { buf + OFF_HF0A, buf + OFF_HF0B };
    float* hb0[2] = { buf + OFF_HB0A, buf + OFF_HB0B };
    float* hf1[2] = { buf + OFF_HF1A, buf + OFF_HF1B };
    float* hb1[2] = { buf + OFF_HB1A, buf + OFF_HB1B };

    // phase 2: recurrent chains
    for (int t = 0; t < T; ++t) {
        const int p = t & 1, q = p ^ 1;
        convlstm_step<64, 64, 64><<<grid0, 256, SMEM_BYTES>>>(
            hf0[p], hf0[q], buf + OFF_CF0, WTs[0], bf0, XGs[0], mask + t * B, t);
    }
    for (int t = 0; t < T; ++t) {
        const int p = t & 1, q = p ^ 1;
        convlstm_step<64, 64, 64><<<grid0, 256, SMEM_BYTES, strm[0]>>>(
            hb0[p], hb0[q], buf + OFF_CB0, WTs[1], bb0, XGs[1], mask + t * B, t);
    }
    for (int t = 0; t < T; ++t) {
        const int p = t & 1, q = p ^ 1;
        convlstm_step<128, 32, 32><<<grid1, 256, SMEM_BYTES, strm[1]>>>(
            hf1[p], hf1[q], buf + OFF_CF1, WTs[2], bf1, XGs[2], mask + t * B, t);
    }
    for (int t = 0; t < T; ++t) {
        const int p = t & 1, q = p ^ 1;
        convlstm_step<128, 32, 32><<<grid1, 256, SMEM_BYTES, strm[2]>>>(
            hb1[p], hb1[q], buf + OFF_CB1, WTs[3], bb1, XGs[3], mask + t * B, t);
    }

    for (int i = 0; i < 3; i++) {
        cudaEventRecord(evJoin[i], strm[i]);
        cudaStreamWaitEvent(0, evJoin[i], 0);
    }

    avg_kernel<<<(unsigned)((ST0 + 255) / 256), 256>>>(hf0[0], hb0[0], out, ST0);
    avg_kernel<<<(unsigned)((ST1 + 255) / 256), 256>>>(hf1[0], hb1[0], out + ST0, ST1);
}